// round 12
// baseline (speedup 1.0000x reference)
#include <cuda_runtime.h>

#define DIM 128
#define NROWS 2048
#define BR 64        // rows per CTA tile
#define BC 32        // cols per CTA tile
#define CPAD 132     // Cs row stride: 4*tx bank-quads -> conflict-free

typedef unsigned long long ull;

// row-major scratch, d contiguous: g_A[n][d] = hi ; g_C[m][d] = hj + b1
__device__ __align__(128) float g_A[NROWS * DIM];
__device__ __align__(128) float g_C[NROWS * DIM];

// ---------------------------------------------------------------------------
// cp.async helpers
// ---------------------------------------------------------------------------
__device__ __forceinline__ void cpa16(void* smem_dst, const void* gmem_src) {
    unsigned s = (unsigned)__cvta_generic_to_shared(smem_dst);
    asm volatile("cp.async.cg.shared.global [%0], [%1], 16;\n"
                 :: "r"(s), "l"(gmem_src));
}
#define CP_COMMIT() asm volatile("cp.async.commit_group;\n" ::: "memory")
#define CP_WAIT0()  asm volatile("cp.async.wait_group 0;\n" ::: "memory")

// ---------------------------------------------------------------------------
// Precompute: side 0 -> g_A[n][d] = z_i @ W1[:128]
//             side 1 -> g_C[m][d] = z_j @ W1[128:] + b1
// grid (64, 2), block 256. Whole W1-half in smem, ONE barrier.
// ---------------------------------------------------------------------------
__global__ void __launch_bounds__(256, 2)
precompute_kernel(const float* __restrict__ z_i,
                  const float* __restrict__ z_j,
                  const float* __restrict__ W1,
                  const float* __restrict__ b1) {
    __shared__ __align__(16) float Zs[32][DIM];     // 16KB
    __shared__ __align__(16) float W1s[DIM][DIM];   // 64KB

    const int side = blockIdx.y;
    const float* z  = side ? z_j : z_i;
    const float* w1 = W1 + side * DIM * DIM;
    const int rowBase = blockIdx.x * 32;
    const int tid = threadIdx.x;

    #pragma unroll
    for (int l = 0; l < 4; l++) {
        int idx = tid + 256 * l;
        int r = idx >> 5, c4 = idx & 31;
        cpa16(&Zs[r][c4 * 4], &z[(size_t)(rowBase + r) * DIM + c4 * 4]);
    }
    #pragma unroll
    for (int l = 0; l < 16; l++) {
        int idx = tid + 256 * l;
        int r = idx >> 5, c4 = idx & 31;
        cpa16(&W1s[r][c4 * 4], &w1[(size_t)r * DIM + c4 * 4]);
    }
    CP_COMMIT();
    CP_WAIT0();
    __syncthreads();   // the ONLY barrier

    const int dg4 = (tid & 15) * 4;
    const int ng  = (tid >> 4) * 2;

    float acc[2][8];
    #pragma unroll
    for (int i = 0; i < 2; i++)
        #pragma unroll
        for (int j = 0; j < 8; j++) acc[i][j] = 0.f;

    #pragma unroll 4
    for (int k = 0; k < DIM; k++) {
        float4 wa = *(const float4*)&W1s[k][dg4];
        float4 wb = *(const float4*)&W1s[k][dg4 + 64];
        float zv0 = Zs[ng][k];
        float zv1 = Zs[ng + 1][k];
        acc[0][0] = fmaf(zv0, wa.x, acc[0][0]);
        acc[0][1] = fmaf(zv0, wa.y, acc[0][1]);
        acc[0][2] = fmaf(zv0, wa.z, acc[0][2]);
        acc[0][3] = fmaf(zv0, wa.w, acc[0][3]);
        acc[0][4] = fmaf(zv0, wb.x, acc[0][4]);
        acc[0][5] = fmaf(zv0, wb.y, acc[0][5]);
        acc[0][6] = fmaf(zv0, wb.z, acc[0][6]);
        acc[0][7] = fmaf(zv0, wb.w, acc[0][7]);
        acc[1][0] = fmaf(zv1, wa.x, acc[1][0]);
        acc[1][1] = fmaf(zv1, wa.y, acc[1][1]);
        acc[1][2] = fmaf(zv1, wa.z, acc[1][2]);
        acc[1][3] = fmaf(zv1, wa.w, acc[1][3]);
        acc[1][4] = fmaf(zv1, wb.x, acc[1][4]);
        acc[1][5] = fmaf(zv1, wb.y, acc[1][5]);
        acc[1][6] = fmaf(zv1, wb.z, acc[1][6]);
        acc[1][7] = fmaf(zv1, wb.w, acc[1][7]);
    }

    float* dst = side ? g_C : g_A;
    float4 bva = make_float4(0.f, 0.f, 0.f, 0.f);
    float4 bvb = bva;
    if (side) {
        bva = *(const float4*)&b1[dg4];
        bvb = *(const float4*)&b1[dg4 + 64];
    }
    #pragma unroll
    for (int i = 0; i < 2; i++) {
        float* p = &dst[(size_t)(rowBase + ng + i) * DIM];
        *(float4*)(p + dg4) = make_float4(acc[i][0] + bva.x, acc[i][1] + bva.y,
                                          acc[i][2] + bva.z, acc[i][3] + bva.w);
        *(float4*)(p + dg4 + 64) = make_float4(acc[i][4] + bvb.x, acc[i][5] + bvb.y,
                                               acc[i][6] + bvb.z, acc[i][7] + bvb.w);
    }
}

// ---------------------------------------------------------------------------
// Main: out[n,m] = sum_d relu(A[n,d] + C[m,d]) * w2[d] + b2
// R8's engine (4x4 thread tile, unroll 2) on 128-thread CTAs, 64x32 tile.
// occ 4 -> 592 slots; 2048 CTAs -> 3.46 waves (tail eff 0.865 vs 0.77).
// Full-depth tile in smem, loaded ONCE, 1 barrier.
// ---------------------------------------------------------------------------
__global__ void __launch_bounds__(128, 4)
mlp_score_kernel(const float* __restrict__ W2, const float* __restrict__ b2p,
                 float* __restrict__ out) {
    __shared__ __align__(16) float As[BR][DIM];     // 32KB
    __shared__ __align__(16) float Cs[BC][CPAD];    // 16.9KB
    __shared__ __align__(16) float Wsm[DIM];        // 0.5KB

    const int tid = threadIdx.x;
    const int tx = tid & 7;         // cols: tx + 8*j, j=0..3
    const int ty = tid >> 3;        // rows: ty*4 + i, i=0..3
    const int rowBase = blockIdx.y * BR;
    const int colBase = blockIdx.x * BC;

    // ---- stage full tiles with cp.async ----
    {
        // As: 64 rows x 32 f4 = 2048 f4 ; 128 threads x 16
        #pragma unroll
        for (int l = 0; l < 16; l++) {
            int idx = tid + 128 * l;
            int r = idx >> 5, c4 = idx & 31;
            cpa16(&As[r][c4 * 4], &g_A[(size_t)(rowBase + r) * DIM + c4 * 4]);
        }
        // Cs: 32 rows x 32 f4 = 1024 f4 ; 128 threads x 8
        #pragma unroll
        for (int l = 0; l < 8; l++) {
            int idx = tid + 128 * l;
            int r = idx >> 5, c4 = idx & 31;
            cpa16(&Cs[r][c4 * 4], &g_C[(size_t)(colBase + r) * DIM + c4 * 4]);
        }
        if (tid < DIM / 4)
            cpa16(&Wsm[tid * 4], &W2[tid * 4]);
        CP_COMMIT();
    }

    const float b2 = __ldg(b2p);
    const float fz = 0.f;
    ull binit;
    asm("mov.b64 %0, {%1, %2};" : "=l"(binit) : "f"(b2), "f"(fz));

    ull acc[4][4];
    #pragma unroll
    for (int i = 0; i < 4; i++)
        #pragma unroll
        for (int j = 0; j < 4; j++) acc[i][j] = binit;

    CP_WAIT0();
    __syncthreads();   // the ONLY barrier

    #pragma unroll 2
    for (int k = 0; k < DIM / 4; k++) {     // 4 d per step (2 d-pairs)
        ulonglong2 av[4], cv[4];
        #pragma unroll
        for (int i = 0; i < 4; i++)
            av[i] = *(const ulonglong2*)&As[ty * 4 + i][k * 4];
        #pragma unroll
        for (int j = 0; j < 4; j++)
            cv[j] = *(const ulonglong2*)&Cs[tx + 8 * j][k * 4];
        ulonglong2 wv = *(const ulonglong2*)&Wsm[k * 4];   // .x=w pair0, .y=w pair1

        #pragma unroll
        for (int i = 0; i < 4; i++) {
            #pragma unroll
            for (int j = 0; j < 4; j++) {
                ull t, r;
                float lo, hi;
                asm("add.rn.f32x2 %0, %1, %2;"
                    : "=l"(t) : "l"(av[i].x), "l"(cv[j].x));
                asm("mov.b64 {%0, %1}, %2;" : "=f"(lo), "=f"(hi) : "l"(t));
                lo = fmaxf(lo, 0.f); hi = fmaxf(hi, 0.f);
                asm("mov.b64 %0, {%1, %2};" : "=l"(r) : "f"(lo), "f"(hi));
                asm("fma.rn.f32x2 %0, %1, %2, %0;"
                    : "+l"(acc[i][j]) : "l"(r), "l"(wv.x));
                asm("add.rn.f32x2 %0, %1, %2;"
                    : "=l"(t) : "l"(av[i].y), "l"(cv[j].y));
                asm("mov.b64 {%0, %1}, %2;" : "=f"(lo), "=f"(hi) : "l"(t));
                lo = fmaxf(lo, 0.f); hi = fmaxf(hi, 0.f);
                asm("mov.b64 %0, {%1, %2};" : "=l"(r) : "f"(lo), "f"(hi));
                asm("fma.rn.f32x2 %0, %1, %2, %0;"
                    : "+l"(acc[i][j]) : "l"(r), "l"(wv.y));
            }
        }
    }

    // epilogue: out = acc.lo + acc.hi  (b2 folded into lo at init)
    #pragma unroll
    for (int i = 0; i < 4; i++) {
        const size_t rowOff = (size_t)(rowBase + ty * 4 + i) * NROWS + colBase;
        #pragma unroll
        for (int j = 0; j < 4; j++) {
            float lo, hi;
            asm("mov.b64 {%0, %1}, %2;" : "=f"(lo), "=f"(hi) : "l"(acc[i][j]));
            out[rowOff + tx + 8 * j] = lo + hi;
        }
    }
}

// ---------------------------------------------------------------------------
extern "C" void kernel_launch(void* const* d_in, const int* in_sizes, int n_in,
                              void* d_out, int out_size) {
    (void)in_sizes; (void)n_in; (void)out_size;
    const float* z_i = (const float*)d_in[0];
    const float* z_j = (const float*)d_in[1];
    const float* W1  = (const float*)d_in[2];
    const float* b1  = (const float*)d_in[3];
    const float* W2  = (const float*)d_in[4];
    const float* b2  = (const float*)d_in[5];
    float* out = (float*)d_out;

    precompute_kernel<<<dim3(64, 2), 256>>>(z_i, z_j, W1, b1);
    mlp_score_kernel<<<dim3(NROWS / BC, NROWS / BR), 128>>>(W2, b2, out);
}

// round 13
// speedup vs baseline: 1.0326x; 1.0326x over previous
#include <cuda_runtime.h>

#define DIM 128
#define NROWS 2048
#define BR 64
#define BC 64
#define CPAD 132           // Cs row stride: conflict-free strided col reads
#define TILES_X (NROWS / BC)           // 32
#define NTILES (TILES_X * (NROWS / BR))  // 1024
#define GRID_MAIN 444      // 148 SMs x 3 CTAs — exactly one wave

typedef unsigned long long ull;

// row-major scratch, d contiguous: g_A[n][d] = hi ; g_C[m][d] = hj + b1
__device__ __align__(128) float g_A[NROWS * DIM];
__device__ __align__(128) float g_C[NROWS * DIM];
__device__ unsigned g_tile_ctr;     // reset by precompute_kernel each launch

// ---------------------------------------------------------------------------
// cp.async helpers
// ---------------------------------------------------------------------------
__device__ __forceinline__ void cpa16(void* smem_dst, const void* gmem_src) {
    unsigned s = (unsigned)__cvta_generic_to_shared(smem_dst);
    asm volatile("cp.async.cg.shared.global [%0], [%1], 16;\n"
                 :: "r"(s), "l"(gmem_src));
}
#define CP_COMMIT() asm volatile("cp.async.commit_group;\n" ::: "memory")
#define CP_WAIT0()  asm volatile("cp.async.wait_group 0;\n" ::: "memory")

// ---------------------------------------------------------------------------
// Precompute: side 0 -> g_A[n][d] = z_i @ W1[:128]
//             side 1 -> g_C[m][d] = z_j @ W1[128:] + b1
// Also resets the persistent-tile counter (stream-ordered before main).
// ---------------------------------------------------------------------------
__global__ void __launch_bounds__(256, 2)
precompute_kernel(const float* __restrict__ z_i,
                  const float* __restrict__ z_j,
                  const float* __restrict__ W1,
                  const float* __restrict__ b1) {
    __shared__ __align__(16) float Zs[32][DIM];     // 16KB
    __shared__ __align__(16) float W1s[DIM][DIM];   // 64KB

    if (blockIdx.x == 0 && blockIdx.y == 0 && threadIdx.x == 0)
        g_tile_ctr = GRID_MAIN;     // main CTA b starts with tile b, then queue

    const int side = blockIdx.y;
    const float* z  = side ? z_j : z_i;
    const float* w1 = W1 + side * DIM * DIM;
    const int rowBase = blockIdx.x * 32;
    const int tid = threadIdx.x;

    #pragma unroll
    for (int l = 0; l < 4; l++) {
        int idx = tid + 256 * l;
        int r = idx >> 5, c4 = idx & 31;
        cpa16(&Zs[r][c4 * 4], &z[(size_t)(rowBase + r) * DIM + c4 * 4]);
    }
    #pragma unroll
    for (int l = 0; l < 16; l++) {
        int idx = tid + 256 * l;
        int r = idx >> 5, c4 = idx & 31;
        cpa16(&W1s[r][c4 * 4], &w1[(size_t)r * DIM + c4 * 4]);
    }
    CP_COMMIT();
    CP_WAIT0();
    __syncthreads();   // the ONLY barrier

    const int dg4 = (tid & 15) * 4;
    const int ng  = (tid >> 4) * 2;

    float acc[2][8];
    #pragma unroll
    for (int i = 0; i < 2; i++)
        #pragma unroll
        for (int j = 0; j < 8; j++) acc[i][j] = 0.f;

    #pragma unroll 4
    for (int k = 0; k < DIM; k++) {
        float4 wa = *(const float4*)&W1s[k][dg4];
        float4 wb = *(const float4*)&W1s[k][dg4 + 64];
        float zv0 = Zs[ng][k];
        float zv1 = Zs[ng + 1][k];
        acc[0][0] = fmaf(zv0, wa.x, acc[0][0]);
        acc[0][1] = fmaf(zv0, wa.y, acc[0][1]);
        acc[0][2] = fmaf(zv0, wa.z, acc[0][2]);
        acc[0][3] = fmaf(zv0, wa.w, acc[0][3]);
        acc[0][4] = fmaf(zv0, wb.x, acc[0][4]);
        acc[0][5] = fmaf(zv0, wb.y, acc[0][5]);
        acc[0][6] = fmaf(zv0, wb.z, acc[0][6]);
        acc[0][7] = fmaf(zv0, wb.w, acc[0][7]);
        acc[1][0] = fmaf(zv1, wa.x, acc[1][0]);
        acc[1][1] = fmaf(zv1, wa.y, acc[1][1]);
        acc[1][2] = fmaf(zv1, wa.z, acc[1][2]);
        acc[1][3] = fmaf(zv1, wa.w, acc[1][3]);
        acc[1][4] = fmaf(zv1, wb.x, acc[1][4]);
        acc[1][5] = fmaf(zv1, wb.y, acc[1][5]);
        acc[1][6] = fmaf(zv1, wb.z, acc[1][6]);
        acc[1][7] = fmaf(zv1, wb.w, acc[1][7]);
    }

    float* dst = side ? g_C : g_A;
    float4 bva = make_float4(0.f, 0.f, 0.f, 0.f);
    float4 bvb = bva;
    if (side) {
        bva = *(const float4*)&b1[dg4];
        bvb = *(const float4*)&b1[dg4 + 64];
    }
    #pragma unroll
    for (int i = 0; i < 2; i++) {
        float* p = &dst[(size_t)(rowBase + ng + i) * DIM];
        *(float4*)(p + dg4) = make_float4(acc[i][0] + bva.x, acc[i][1] + bva.y,
                                          acc[i][2] + bva.z, acc[i][3] + bva.w);
        *(float4*)(p + dg4 + 64) = make_float4(acc[i][4] + bvb.x, acc[i][5] + bvb.y,
                                               acc[i][6] + bvb.z, acc[i][7] + bvb.w);
    }
}

// ---------------------------------------------------------------------------
// Main (persistent): out[n,m] = sum_d relu(A[n,d] + C[m,d]) * w2[d] + b2
// 444 CTAs (one full wave at occ 3) pull 64x64 tiles from a global queue —
// removes the ceil(2.31)->3 wave quantization that capped R8 at issue=77%.
// Engine identical to R8: 4x4 thread tile, d-pair packing, unroll 2.
// ---------------------------------------------------------------------------
__global__ void __launch_bounds__(256, 3)
mlp_score_kernel(const float* __restrict__ W2, const float* __restrict__ b2p,
                 float* __restrict__ out) {
    __shared__ __align__(16) float As[BR][DIM];     // 32KB
    __shared__ __align__(16) float Cs[BC][CPAD];    // 33.8KB
    __shared__ __align__(16) float Wsm[DIM];        // 0.5KB
    __shared__ unsigned sTile;

    const int tid = threadIdx.x;
    const int tx = tid & 15;        // cols: tx + 16*j, j=0..3
    const int ty = tid >> 4;        // rows: ty*4 + i, i=0..3

    // W2 staged once (joins first tile's commit group)
    if (tid < DIM / 4)
        cpa16(&Wsm[tid * 4], &W2[tid * 4]);

    const float b2 = __ldg(b2p);
    const float fz = 0.f;
    ull binit;
    asm("mov.b64 %0, {%1, %2};" : "=l"(binit) : "f"(b2), "f"(fz));

    unsigned tile = blockIdx.x;

    while (tile < NTILES) {
        const int rowBase = (int)(tile / TILES_X) * BR;
        const int colBase = (int)(tile % TILES_X) * BC;

        // ---- stage tile with cp.async ----
        {
            const int r = tid >> 2;          // 0..63
            const int f4 = tid & 3;
            #pragma unroll
            for (int l = 0; l < 8; l++) {
                int c4 = f4 + 4 * l;
                cpa16(&As[r][c4 * 4], &g_A[(size_t)(rowBase + r) * DIM + c4 * 4]);
            }
            #pragma unroll
            for (int l = 0; l < 8; l++) {
                int c4 = f4 + 4 * l;
                cpa16(&Cs[r][c4 * 4], &g_C[(size_t)(colBase + r) * DIM + c4 * 4]);
            }
            CP_COMMIT();
        }

        ull acc[4][4];
        #pragma unroll
        for (int i = 0; i < 4; i++)
            #pragma unroll
            for (int j = 0; j < 4; j++) acc[i][j] = binit;

        CP_WAIT0();
        __syncthreads();   // tile visible

        #pragma unroll 2
        for (int k = 0; k < DIM / 4; k++) {     // 4 d per step (2 d-pairs)
            ulonglong2 av[4], cv[4];
            #pragma unroll
            for (int i = 0; i < 4; i++)
                av[i] = *(const ulonglong2*)&As[ty * 4 + i][k * 4];
            #pragma unroll
            for (int j = 0; j < 4; j++)
                cv[j] = *(const ulonglong2*)&Cs[tx + 16 * j][k * 4];
            ulonglong2 wv = *(const ulonglong2*)&Wsm[k * 4];

            #pragma unroll
            for (int i = 0; i < 4; i++) {
                #pragma unroll
                for (int j = 0; j < 4; j++) {
                    ull t, r;
                    float lo, hi;
                    asm("add.rn.f32x2 %0, %1, %2;"
                        : "=l"(t) : "l"(av[i].x), "l"(cv[j].x));
                    asm("mov.b64 {%0, %1}, %2;" : "=f"(lo), "=f"(hi) : "l"(t));
                    lo = fmaxf(lo, 0.f); hi = fmaxf(hi, 0.f);
                    asm("mov.b64 %0, {%1, %2};" : "=l"(r) : "f"(lo), "f"(hi));
                    asm("fma.rn.f32x2 %0, %1, %2, %0;"
                        : "+l"(acc[i][j]) : "l"(r), "l"(wv.x));
                    asm("add.rn.f32x2 %0, %1, %2;"
                        : "=l"(t) : "l"(av[i].y), "l"(cv[j].y));
                    asm("mov.b64 {%0, %1}, %2;" : "=f"(lo), "=f"(hi) : "l"(t));
                    lo = fmaxf(lo, 0.f); hi = fmaxf(hi, 0.f);
                    asm("mov.b64 %0, {%1, %2};" : "=l"(r) : "f"(lo), "f"(hi));
                    asm("fma.rn.f32x2 %0, %1, %2, %0;"
                        : "+l"(acc[i][j]) : "l"(r), "l"(wv.y));
                }
            }
        }

        // epilogue: out = acc.lo + acc.hi  (b2 folded into lo at init)
        #pragma unroll
        for (int i = 0; i < 4; i++) {
            const size_t rowOff = (size_t)(rowBase + ty * 4 + i) * NROWS + colBase;
            #pragma unroll
            for (int j = 0; j < 4; j++) {
                float lo, hi;
                asm("mov.b64 {%0, %1}, %2;" : "=f"(lo), "=f"(hi) : "l"(acc[i][j]));
                out[rowOff + tx + 16 * j] = lo + hi;
            }
        }

        // ---- next tile from the queue ----
        if (tid == 0)
            sTile = atomicAdd(&g_tile_ctr, 1u);
        __syncthreads();   // all warps done with smem; sTile visible
        tile = sTile;
    }
}

// ---------------------------------------------------------------------------
extern "C" void kernel_launch(void* const* d_in, const int* in_sizes, int n_in,
                              void* d_out, int out_size) {
    (void)in_sizes; (void)n_in; (void)out_size;
    const float* z_i = (const float*)d_in[0];
    const float* z_j = (const float*)d_in[1];
    const float* W1  = (const float*)d_in[2];
    const float* b1  = (const float*)d_in[3];
    const float* W2  = (const float*)d_in[4];
    const float* b2  = (const float*)d_in[5];
    float* out = (float*)d_out;

    precompute_kernel<<<dim3(64, 2), 256>>>(z_i, z_j, W1, b1);
    mlp_score_kernel<<<GRID_MAIN, 256>>>(W2, b2, out);
}

// round 14
// speedup vs baseline: 1.0539x; 1.0207x over previous
#include <cuda_runtime.h>

#define DIM 128
#define NROWS 2048
#define BR 64
#define BC 64
#define CPAD 132     // Cs row stride: conflict-free strided col reads

typedef unsigned long long ull;

// row-major scratch, d contiguous: g_A[n][d] = hi ; g_C[m][d] = hj + b1
__device__ __align__(128) float g_A[NROWS * DIM];
__device__ __align__(128) float g_C[NROWS * DIM];

// ---------------------------------------------------------------------------
// cp.async helpers
// ---------------------------------------------------------------------------
__device__ __forceinline__ void cpa16(void* smem_dst, const void* gmem_src) {
    unsigned s = (unsigned)__cvta_generic_to_shared(smem_dst);
    asm volatile("cp.async.cg.shared.global [%0], [%1], 16;\n"
                 :: "r"(s), "l"(gmem_src));
}
#define CP_COMMIT() asm volatile("cp.async.commit_group;\n" ::: "memory")
#define CP_WAIT0()  asm volatile("cp.async.wait_group 0;\n" ::: "memory")

// ---------------------------------------------------------------------------
// Precompute: side 0 -> g_A[n][d] = z_i @ W1[:128]
//             side 1 -> g_C[m][d] = z_j @ W1[128:] + b1
// grid (128, 2) = 256 CTAs of 16 rows: all 148 SMs covered (~1.7 CTA/SM)
// vs the old 128-CTA config that idled 20 SMs. Whole W1-half in smem,
// ONE barrier. Thread: 1 row x 8 d.
// ---------------------------------------------------------------------------
__global__ void __launch_bounds__(256, 2)
precompute_kernel(const float* __restrict__ z_i,
                  const float* __restrict__ z_j,
                  const float* __restrict__ W1,
                  const float* __restrict__ b1) {
    __shared__ __align__(16) float Zs[16][DIM];     // 8KB
    __shared__ __align__(16) float W1s[DIM][DIM];   // 64KB

    const int side = blockIdx.y;
    const float* z  = side ? z_j : z_i;
    const float* w1 = W1 + side * DIM * DIM;
    const int rowBase = blockIdx.x * 16;
    const int tid = threadIdx.x;

    // stage Zs (512 f4) + W1s (4096 f4)
    #pragma unroll
    for (int l = 0; l < 2; l++) {
        int idx = tid + 256 * l;
        int r = idx >> 5, c4 = idx & 31;
        cpa16(&Zs[r][c4 * 4], &z[(size_t)(rowBase + r) * DIM + c4 * 4]);
    }
    #pragma unroll
    for (int l = 0; l < 16; l++) {
        int idx = tid + 256 * l;
        int r = idx >> 5, c4 = idx & 31;
        cpa16(&W1s[r][c4 * 4], &w1[(size_t)r * DIM + c4 * 4]);
    }
    CP_COMMIT();
    CP_WAIT0();
    __syncthreads();   // the ONLY barrier

    const int dg4 = (tid & 15) * 4;       // d: dg4..+3 and dg4+64..+67
    const int ng  = tid >> 4;             // 1 row

    float acc[8];
    #pragma unroll
    for (int j = 0; j < 8; j++) acc[j] = 0.f;

    #pragma unroll 4
    for (int k = 0; k < DIM; k++) {
        float4 wa = *(const float4*)&W1s[k][dg4];
        float4 wb = *(const float4*)&W1s[k][dg4 + 64];
        float zv = Zs[ng][k];
        acc[0] = fmaf(zv, wa.x, acc[0]);
        acc[1] = fmaf(zv, wa.y, acc[1]);
        acc[2] = fmaf(zv, wa.z, acc[2]);
        acc[3] = fmaf(zv, wa.w, acc[3]);
        acc[4] = fmaf(zv, wb.x, acc[4]);
        acc[5] = fmaf(zv, wb.y, acc[5]);
        acc[6] = fmaf(zv, wb.z, acc[6]);
        acc[7] = fmaf(zv, wb.w, acc[7]);
    }

    float* dst = side ? g_C : g_A;
    float4 bva = make_float4(0.f, 0.f, 0.f, 0.f);
    float4 bvb = bva;
    if (side) {
        bva = *(const float4*)&b1[dg4];
        bvb = *(const float4*)&b1[dg4 + 64];
    }
    float* p = &dst[(size_t)(rowBase + ng) * DIM];
    *(float4*)(p + dg4) = make_float4(acc[0] + bva.x, acc[1] + bva.y,
                                      acc[2] + bva.z, acc[3] + bva.w);
    *(float4*)(p + dg4 + 64) = make_float4(acc[4] + bvb.x, acc[5] + bvb.y,
                                           acc[6] + bvb.z, acc[7] + bvb.w);
}

// ---------------------------------------------------------------------------
// Main: out[n,m] = sum_d relu(A[n,d] + C[m,d]) * w2[d] + b2
// R8 exactly: 64x64 full-depth tile, loaded ONCE, 1 barrier; 4x4 thread
// tile with d-pair packed accumulators; unroll 2 (L0 I$-safe); occ 3.
// This config is at the structural ceiling: 1024 tiles / 444 slots -> 3
// waves is irreducible; all alternative shapes re-derive to <= this.
// ---------------------------------------------------------------------------
__global__ void __launch_bounds__(256, 3)
mlp_score_kernel(const float* __restrict__ W2, const float* __restrict__ b2p,
                 float* __restrict__ out) {
    __shared__ __align__(16) float As[BR][DIM];     // 32KB
    __shared__ __align__(16) float Cs[BC][CPAD];    // 33.8KB
    __shared__ __align__(16) float Wsm[DIM];        // 0.5KB

    const int tid = threadIdx.x;
    const int tx = tid & 15;        // cols: tx + 16*j, j=0..3
    const int ty = tid >> 4;        // rows: ty*4 + i, i=0..3
    const int rowBase = blockIdx.y * BR;
    const int colBase = blockIdx.x * BC;

    // ---- stage full tiles with cp.async ----
    {
        const int r = tid >> 2;          // 0..63
        const int f4 = tid & 3;
        #pragma unroll
        for (int l = 0; l < 8; l++) {
            int c4 = f4 + 4 * l;
            cpa16(&As[r][c4 * 4], &g_A[(size_t)(rowBase + r) * DIM + c4 * 4]);
        }
        #pragma unroll
        for (int l = 0; l < 8; l++) {
            int c4 = f4 + 4 * l;
            cpa16(&Cs[r][c4 * 4], &g_C[(size_t)(colBase + r) * DIM + c4 * 4]);
        }
        if (tid < DIM / 4)
            cpa16(&Wsm[tid * 4], &W2[tid * 4]);
        CP_COMMIT();
    }

    const float b2 = __ldg(b2p);
    const float fz = 0.f;
    ull binit;
    asm("mov.b64 %0, {%1, %2};" : "=l"(binit) : "f"(b2), "f"(fz));

    ull acc[4][4];
    #pragma unroll
    for (int i = 0; i < 4; i++)
        #pragma unroll
        for (int j = 0; j < 4; j++) acc[i][j] = binit;

    CP_WAIT0();
    __syncthreads();   // the ONLY barrier

    #pragma unroll 2
    for (int k = 0; k < DIM / 4; k++) {     // 4 d per step (2 d-pairs)
        ulonglong2 av[4], cv[4];
        #pragma unroll
        for (int i = 0; i < 4; i++)
            av[i] = *(const ulonglong2*)&As[ty * 4 + i][k * 4];
        #pragma unroll
        for (int j = 0; j < 4; j++)
            cv[j] = *(const ulonglong2*)&Cs[tx + 16 * j][k * 4];
        ulonglong2 wv = *(const ulonglong2*)&Wsm[k * 4];   // .x=w pair0, .y=w pair1

        #pragma unroll
        for (int i = 0; i < 4; i++) {
            #pragma unroll
            for (int j = 0; j < 4; j++) {
                ull t, r;
                float lo, hi;
                asm("add.rn.f32x2 %0, %1, %2;"
                    : "=l"(t) : "l"(av[i].x), "l"(cv[j].x));
                asm("mov.b64 {%0, %1}, %2;" : "=f"(lo), "=f"(hi) : "l"(t));
                lo = fmaxf(lo, 0.f); hi = fmaxf(hi, 0.f);
                asm("mov.b64 %0, {%1, %2};" : "=l"(r) : "f"(lo), "f"(hi));
                asm("fma.rn.f32x2 %0, %1, %2, %0;"
                    : "+l"(acc[i][j]) : "l"(r), "l"(wv.x));
                asm("add.rn.f32x2 %0, %1, %2;"
                    : "=l"(t) : "l"(av[i].y), "l"(cv[j].y));
                asm("mov.b64 {%0, %1}, %2;" : "=f"(lo), "=f"(hi) : "l"(t));
                lo = fmaxf(lo, 0.f); hi = fmaxf(hi, 0.f);
                asm("mov.b64 %0, {%1, %2};" : "=l"(r) : "f"(lo), "f"(hi));
                asm("fma.rn.f32x2 %0, %1, %2, %0;"
                    : "+l"(acc[i][j]) : "l"(r), "l"(wv.y));
            }
        }
    }

    // epilogue: out = acc.lo + acc.hi  (b2 folded into lo at init)
    #pragma unroll
    for (int i = 0; i < 4; i++) {
        const size_t rowOff = (size_t)(rowBase + ty * 4 + i) * NROWS + colBase;
        #pragma unroll
        for (int j = 0; j < 4; j++) {
            float lo, hi;
            asm("mov.b64 {%0, %1}, %2;" : "=f"(lo), "=f"(hi) : "l"(acc[i][j]));
            out[rowOff + tx + 16 * j] = lo + hi;
        }
    }
}

// ---------------------------------------------------------------------------
extern "C" void kernel_launch(void* const* d_in, const int* in_sizes, int n_in,
                              void* d_out, int out_size) {
    (void)in_sizes; (void)n_in; (void)out_size;
    const float* z_i = (const float*)d_in[0];
    const float* z_j = (const float*)d_in[1];
    const float* W1  = (const float*)d_in[2];
    const float* b1  = (const float*)d_in[3];
    const float* W2  = (const float*)d_in[4];
    const float* b2  = (const float*)d_in[5];
    float* out = (float*)d_out;

    precompute_kernel<<<dim3(128, 2), 256>>>(z_i, z_j, W1, b1);
    mlp_score_kernel<<<dim3(NROWS / BC, NROWS / BR), 256>>>(W2, b2, out);
}

// round 15
// speedup vs baseline: 1.1316x; 1.0737x over previous
#include <cuda_runtime.h>

#define DIM 128
#define NROWS 2048
#define BR 64
#define BC 64
#define CPAD 132     // Cs row stride: conflict-free strided col reads

typedef unsigned long long ull;

// row-major scratch, d contiguous: g_A[n][d] = hi ; g_C[m][d] = hj + b1
__device__ __align__(128) float g_A[NROWS * DIM];
__device__ __align__(128) float g_C[NROWS * DIM];

// ---------------------------------------------------------------------------
// cp.async helpers
// ---------------------------------------------------------------------------
__device__ __forceinline__ void cpa16(void* smem_dst, const void* gmem_src) {
    unsigned s = (unsigned)__cvta_generic_to_shared(smem_dst);
    asm volatile("cp.async.cg.shared.global [%0], [%1], 16;\n"
                 :: "r"(s), "l"(gmem_src));
}
#define CP_COMMIT() asm volatile("cp.async.commit_group;\n" ::: "memory")
#define CP_WAIT0()  asm volatile("cp.async.wait_group 0;\n" ::: "memory")

// ---------------------------------------------------------------------------
// Precompute: side 0 -> g_A[n][d] = z_i @ W1[:128]
//             side 1 -> g_C[m][d] = z_j @ W1[128:] + b1
// grid (64, 2), block 256, 32 rows/CTA, thread = 2 rows x 8 d — the measured
// best shape (R8). NEW: d-pair packed fma.f32x2 halves fma-pipe work
// (precompute was fma-bound at ~4.7us; packed -> ~2.4us).
// Whole W1-half in smem, ONE barrier.
// ---------------------------------------------------------------------------
__global__ void __launch_bounds__(256, 2)
precompute_kernel(const float* __restrict__ z_i,
                  const float* __restrict__ z_j,
                  const float* __restrict__ W1,
                  const float* __restrict__ b1) {
    __shared__ __align__(16) float Zs[32][DIM];     // 16KB
    __shared__ __align__(16) float W1s[DIM][DIM];   // 64KB

    const int side = blockIdx.y;
    const float* z  = side ? z_j : z_i;
    const float* w1 = W1 + side * DIM * DIM;
    const int rowBase = blockIdx.x * 32;
    const int tid = threadIdx.x;

    #pragma unroll
    for (int l = 0; l < 4; l++) {
        int idx = tid + 256 * l;
        int r = idx >> 5, c4 = idx & 31;
        cpa16(&Zs[r][c4 * 4], &z[(size_t)(rowBase + r) * DIM + c4 * 4]);
    }
    #pragma unroll
    for (int l = 0; l < 16; l++) {
        int idx = tid + 256 * l;
        int r = idx >> 5, c4 = idx & 31;
        cpa16(&W1s[r][c4 * 4], &w1[(size_t)r * DIM + c4 * 4]);
    }
    CP_COMMIT();
    CP_WAIT0();
    __syncthreads();   // the ONLY barrier

    const int dg4 = (tid & 15) * 4;       // d: dg4..+3 and dg4+64..+67
    const int ng  = (tid >> 4) * 2;       // 2 rows

    // acc[i][p]: row i, d-pair p (p=0,1 -> dg4; p=2,3 -> dg4+64)
    ull acc[2][4];
    #pragma unroll
    for (int i = 0; i < 2; i++)
        #pragma unroll
        for (int p = 0; p < 4; p++) acc[i][p] = 0ull;

    #pragma unroll 4
    for (int k = 0; k < DIM; k++) {
        ulonglong2 wa = *(const ulonglong2*)&W1s[k][dg4];        // pairs 0,1
        ulonglong2 wb = *(const ulonglong2*)&W1s[k][dg4 + 64];   // pairs 2,3
        float zv0 = Zs[ng][k];
        float zv1 = Zs[ng + 1][k];
        ull z0, z1;
        asm("mov.b64 %0, {%1, %1};" : "=l"(z0) : "f"(zv0));
        asm("mov.b64 %0, {%1, %1};" : "=l"(z1) : "f"(zv1));
        asm("fma.rn.f32x2 %0, %1, %2, %0;" : "+l"(acc[0][0]) : "l"(wa.x), "l"(z0));
        asm("fma.rn.f32x2 %0, %1, %2, %0;" : "+l"(acc[0][1]) : "l"(wa.y), "l"(z0));
        asm("fma.rn.f32x2 %0, %1, %2, %0;" : "+l"(acc[0][2]) : "l"(wb.x), "l"(z0));
        asm("fma.rn.f32x2 %0, %1, %2, %0;" : "+l"(acc[0][3]) : "l"(wb.y), "l"(z0));
        asm("fma.rn.f32x2 %0, %1, %2, %0;" : "+l"(acc[1][0]) : "l"(wa.x), "l"(z1));
        asm("fma.rn.f32x2 %0, %1, %2, %0;" : "+l"(acc[1][1]) : "l"(wa.y), "l"(z1));
        asm("fma.rn.f32x2 %0, %1, %2, %0;" : "+l"(acc[1][2]) : "l"(wb.x), "l"(z1));
        asm("fma.rn.f32x2 %0, %1, %2, %0;" : "+l"(acc[1][3]) : "l"(wb.y), "l"(z1));
    }

    // fold b1 in packed form (zero for side 0)
    ull bp[4] = {0ull, 0ull, 0ull, 0ull};
    if (side) {
        ulonglong2 ba = *(const ulonglong2*)&b1[dg4];
        ulonglong2 bb = *(const ulonglong2*)&b1[dg4 + 64];
        bp[0] = ba.x; bp[1] = ba.y; bp[2] = bb.x; bp[3] = bb.y;
    }
    float* dst = side ? g_C : g_A;
    #pragma unroll
    for (int i = 0; i < 2; i++) {
        ull o[4];
        #pragma unroll
        for (int p = 0; p < 4; p++)
            asm("add.rn.f32x2 %0, %1, %2;" : "=l"(o[p]) : "l"(acc[i][p]), "l"(bp[p]));
        float* pr = &dst[(size_t)(rowBase + ng + i) * DIM];
        *(ulonglong2*)(pr + dg4)      = make_ulonglong2(o[0], o[1]);
        *(ulonglong2*)(pr + dg4 + 64) = make_ulonglong2(o[2], o[3]);
    }
}

// ---------------------------------------------------------------------------
// Main: out[n,m] = sum_d relu(A[n,d] + C[m,d]) * w2[d] + b2
// R8 exactly (best measured, at the structural ceiling): 64x64 full-depth
// tile, loaded ONCE, 1 barrier; 4x4 thread tile, d-pair packed accumulators;
// unroll 2 (L0 I$-safe); occ 3.
// ---------------------------------------------------------------------------
__global__ void __launch_bounds__(256, 3)
mlp_score_kernel(const float* __restrict__ W2, const float* __restrict__ b2p,
                 float* __restrict__ out) {
    __shared__ __align__(16) float As[BR][DIM];     // 32KB
    __shared__ __align__(16) float Cs[BC][CPAD];    // 33.8KB
    __shared__ __align__(16) float Wsm[DIM];        // 0.5KB

    const int tid = threadIdx.x;
    const int tx = tid & 15;        // cols: tx + 16*j, j=0..3
    const int ty = tid >> 4;        // rows: ty*4 + i, i=0..3
    const int rowBase = blockIdx.y * BR;
    const int colBase = blockIdx.x * BC;

    // ---- stage full tiles with cp.async ----
    {
        const int r = tid >> 2;          // 0..63
        const int f4 = tid & 3;
        #pragma unroll
        for (int l = 0; l < 8; l++) {
            int c4 = f4 + 4 * l;
            cpa16(&As[r][c4 * 4], &g_A[(size_t)(rowBase + r) * DIM + c4 * 4]);
        }
        #pragma unroll
        for (int l = 0; l < 8; l++) {
            int c4 = f4 + 4 * l;
            cpa16(&Cs[r][c4 * 4], &g_C[(size_t)(colBase + r) * DIM + c4 * 4]);
        }
        if (tid < DIM / 4)
            cpa16(&Wsm[tid * 4], &W2[tid * 4]);
        CP_COMMIT();
    }

    const float b2 = __ldg(b2p);
    const float fz = 0.f;
    ull binit;
    asm("mov.b64 %0, {%1, %2};" : "=l"(binit) : "f"(b2), "f"(fz));

    ull acc[4][4];
    #pragma unroll
    for (int i = 0; i < 4; i++)
        #pragma unroll
        for (int j = 0; j < 4; j++) acc[i][j] = binit;

    CP_WAIT0();
    __syncthreads();   // the ONLY barrier

    #pragma unroll 2
    for (int k = 0; k < DIM / 4; k++) {     // 4 d per step (2 d-pairs)
        ulonglong2 av[4], cv[4];
        #pragma unroll
        for (int i = 0; i < 4; i++)
            av[i] = *(const ulonglong2*)&As[ty * 4 + i][k * 4];
        #pragma unroll
        for (int j = 0; j < 4; j++)
            cv[j] = *(const ulonglong2*)&Cs[tx + 16 * j][k * 4];
        ulonglong2 wv = *(const ulonglong2*)&Wsm[k * 4];   // .x=w pair0, .y=w pair1

        #pragma unroll
        for (int i = 0; i < 4; i++) {
            #pragma unroll
            for (int j = 0; j < 4; j++) {
                ull t, r;
                float lo, hi;
                asm("add.rn.f32x2 %0, %1, %2;"
                    : "=l"(t) : "l"(av[i].x), "l"(cv[j].x));
                asm("mov.b64 {%0, %1}, %2;" : "=f"(lo), "=f"(hi) : "l"(t));
                lo = fmaxf(lo, 0.f); hi = fmaxf(hi, 0.f);
                asm("mov.b64 %0, {%1, %2};" : "=l"(r) : "f"(lo), "f"(hi));
                asm("fma.rn.f32x2 %0, %1, %2, %0;"
                    : "+l"(acc[i][j]) : "l"(r), "l"(wv.x));
                asm("add.rn.f32x2 %0, %1, %2;"
                    : "=l"(t) : "l"(av[i].y), "l"(cv[j].y));
                asm("mov.b64 {%0, %1}, %2;" : "=f"(lo), "=f"(hi) : "l"(t));
                lo = fmaxf(lo, 0.f); hi = fmaxf(hi, 0.f);
                asm("mov.b64 %0, {%1, %2};" : "=l"(r) : "f"(lo), "f"(hi));
                asm("fma.rn.f32x2 %0, %1, %2, %0;"
                    : "+l"(acc[i][j]) : "l"(r), "l"(wv.y));
            }
        }
    }

    // epilogue: out = acc.lo + acc.hi  (b2 folded into lo at init)
    #pragma unroll
    for (int i = 0; i < 4; i++) {
        const size_t rowOff = (size_t)(rowBase + ty * 4 + i) * NROWS + colBase;
        #pragma unroll
        for (int j = 0; j < 4; j++) {
            float lo, hi;
            asm("mov.b64 {%0, %1}, %2;" : "=f"(lo), "=f"(hi) : "l"(acc[i][j]));
            out[rowOff + tx + 16 * j] = lo + hi;
        }
    }
}

// ---------------------------------------------------------------------------
extern "C" void kernel_launch(void* const* d_in, const int* in_sizes, int n_in,
                              void* d_out, int out_size) {
    (void)in_sizes; (void)n_in; (void)out_size;
    const float* z_i = (const float*)d_in[0];
    const float* z_j = (const float*)d_in[1];
    const float* W1  = (const float*)d_in[2];
    const float* b1  = (const float*)d_in[3];
    const float* W2  = (const float*)d_in[4];
    const float* b2  = (const float*)d_in[5];
    float* out = (float*)d_out;

    precompute_kernel<<<dim3(64, 2), 256>>>(z_i, z_j, W1, b1);
    mlp_score_kernel<<<dim3(NROWS / BC, NROWS / BR), 256>>>(W2, b2, out);
}